// round 9
// baseline (speedup 1.0000x reference)
#include <cuda_runtime.h>
#include <cuda_bf16.h>
#include <cstdint>

#define Bn 16
#define Cn 256
#define Hn 96
#define Wn 96
#define HWc 9216
#define CHWc 2359296   // Cn*HWc
#define TOTc 37748736  // Bn*CHWc

// ---------------- scratch ----------------
__device__ float g_xp[TOTc];
__device__ float g_gate[TOTc];
__device__ float g_sw[TOTc];
__device__ float g_sh[TOTc];
__device__ float g_fd[TOTc];
__device__ float g_o1[TOTc];
__device__ float g_ss1[Bn*Cn*2];
__device__ float g_ss2[Bn*Cn*2];

__device__ __forceinline__ float sigmoid_f(float x) { return 1.0f / (1.0f + __expf(-x)); }
__device__ __forceinline__ float silu_f(float x)    { return x / (1.0f + __expf(-x)); }

__device__ __forceinline__ uint32_t smem_u32(const void* p) {
    uint32_t a;
    asm("{ .reg .u64 t; cvta.to.shared.u64 t, %1; cvt.u32.u64 %0, t; }" : "=r"(a) : "l"(p));
    return a;
}
__device__ __forceinline__ void ldsm4(uint32_t &r0, uint32_t &r1, uint32_t &r2, uint32_t &r3, uint32_t addr) {
    asm volatile("ldmatrix.sync.aligned.m8n8.x4.shared.b16 {%0,%1,%2,%3}, [%4];"
                 : "=r"(r0), "=r"(r1), "=r"(r2), "=r"(r3) : "r"(addr));
}
__device__ __forceinline__ void ldsm2t(uint32_t &r0, uint32_t &r1, uint32_t addr) {
    asm volatile("ldmatrix.sync.aligned.m8n8.x2.trans.shared.b16 {%0,%1}, [%2];"
                 : "=r"(r0), "=r"(r1) : "r"(addr));
}
__device__ __forceinline__ void mma16816(float* d, const uint32_t* a, const uint32_t* b) {
    asm volatile("mma.sync.aligned.m16n8k16.row.col.f32.bf16.bf16.f32 "
                 "{%0,%1,%2,%3}, {%4,%5,%6,%7}, {%8,%9}, {%0,%1,%2,%3};"
                 : "+f"(d[0]), "+f"(d[1]), "+f"(d[2]), "+f"(d[3])
                 : "r"(a[0]), "r"(a[1]), "r"(a[2]), "r"(a[3]), "r"(b[0]), "r"(b[1]));
}

// ================ fused-conversion bf16 warp-MMA GEMM ================
// C[b][m][n] = sum_k A[m][k] * B[b][k][n]. A fp32 [256,256]; B fp32 [b][256][9216].
// BM=128, BN=128, BK=32 panel; 8 panels; per panel 3 split passes (AhBh, AlBh, AhBl).
// modeB=1: B row k transformed by silu(affine) with ss[(b*Cn+k)].
// modeC=1: C = sigmoid(C + gbias[m]).
#define APITCH 40    // bf16/row for A smem (80B stride)
#define BPITCH 136   // bf16/row for B smem (272B stride; 17 mod 8 = 1 -> ldsm-trans conflict-free)
#define A_BUF 10240  // 128*40*2 bytes
#define B_BUF 8704   // 32*136*2 bytes
#define OFF_AH 0
#define OFF_AL (2*A_BUF)
#define OFF_BH (4*A_BUF)
#define OFF_BL (4*A_BUF + 2*B_BUF)
#define GSM_TOT (4*A_BUF + 4*B_BUF)   // 75776 bytes

__global__ __launch_bounds__(256) void gemm_fused_kernel(
    const float* __restrict__ Aw, const float* __restrict__ Bsrc,
    float* __restrict__ Cd, const float* __restrict__ ss,
    const float* __restrict__ gbias, int modeB, int modeC)
{
    extern __shared__ __align__(16) char gsm[];
    const uint32_t su = smem_u32(gsm);
    const int tid = threadIdx.x, lane = tid & 31, warp = tid >> 5;
    const int wm = (warp & 1) * 64, wn = (warp >> 1) * 32;
    const int n0 = blockIdx.x * 128, bm = blockIdx.y * 128, bb = blockIdx.z;

    // staging indices
    const int m_a = tid >> 1, kc_a = (tid & 1) * 16;   // A: row m, 16-col chunk
    const int k_b = tid >> 3, nc_b = (tid & 7) * 16;   // B: k-row, 16-col chunk

    float acc[4][4][4];
#pragma unroll
    for (int i = 0; i < 4; i++)
#pragma unroll
        for (int j = 0; j < 4; j++)
#pragma unroll
            for (int k = 0; k < 4; k++) acc[i][j][k] = 0.0f;

    float4 rA[4], rB[4];
    // load panel 0
    {
        const float* ap = Aw + (size_t)(bm + m_a) * Cn + kc_a;
        rA[0] = *(const float4*)ap;      rA[1] = *(const float4*)(ap + 4);
        rA[2] = *(const float4*)(ap + 8); rA[3] = *(const float4*)(ap + 12);
        const float* bp = Bsrc + (size_t)bb * CHWc + (size_t)k_b * HWc + n0 + nc_b;
        rB[0] = *(const float4*)bp;      rB[1] = *(const float4*)(bp + 4);
        rB[2] = *(const float4*)(bp + 8); rB[3] = *(const float4*)(bp + 12);
    }

    for (int p = 0; p < 8; p++) {
        const int buf = p & 1;
        // ---- convert + STS current panel
        {
            float bscale = 1.0f, bshift = 0.0f;
            if (modeB) {
                float2 s = *(const float2*)&ss[(bb * Cn + p * 32 + k_b) * 2];
                bscale = s.x; bshift = s.y;
            }
            __nv_bfloat16* pAh = (__nv_bfloat16*)(gsm + OFF_AH + buf * A_BUF) + m_a * APITCH + kc_a;
            __nv_bfloat16* pAl = (__nv_bfloat16*)(gsm + OFF_AL + buf * A_BUF) + m_a * APITCH + kc_a;
            __nv_bfloat16* pBh = (__nv_bfloat16*)(gsm + OFF_BH + buf * B_BUF) + k_b * BPITCH + nc_b;
            __nv_bfloat16* pBl = (__nv_bfloat16*)(gsm + OFF_BL + buf * B_BUF) + k_b * BPITCH + nc_b;
            const float* fa = (const float*)rA;
            const float* fb = (const float*)rB;
#pragma unroll
            for (int j = 0; j < 16; j++) {
                float va = fa[j];
                __nv_bfloat16 ha = __float2bfloat16(va);
                pAh[j] = ha;
                pAl[j] = __float2bfloat16(va - __bfloat162float(ha));
                float vb = fb[j];
                if (modeB) vb = silu_f(fmaf(vb, bscale, bshift));
                __nv_bfloat16 hb = __float2bfloat16(vb);
                pBh[j] = hb;
                pBl[j] = __float2bfloat16(vb - __bfloat162float(hb));
            }
        }
        __syncthreads();
        // ---- prefetch next panel
        if (p < 7) {
            const int k0 = (p + 1) * 32;
            const float* ap = Aw + (size_t)(bm + m_a) * Cn + k0 + kc_a;
            rA[0] = *(const float4*)ap;      rA[1] = *(const float4*)(ap + 4);
            rA[2] = *(const float4*)(ap + 8); rA[3] = *(const float4*)(ap + 12);
            const float* bp = Bsrc + (size_t)bb * CHWc + (size_t)(k0 + k_b) * HWc + n0 + nc_b;
            rB[0] = *(const float4*)bp;      rB[1] = *(const float4*)(bp + 4);
            rB[2] = *(const float4*)(bp + 8); rB[3] = *(const float4*)(bp + 12);
        }
        // ---- 3 split passes over this panel
#pragma unroll
        for (int pass = 0; pass < 3; pass++) {
            const uint32_t ab = su + (pass == 1 ? OFF_AL : OFF_AH) + buf * A_BUF;
            const uint32_t bbse = su + (pass == 2 ? OFF_BL : OFF_BH) + buf * B_BUF;
#pragma unroll
            for (int ks = 0; ks < 2; ks++) {
                uint32_t af[4][4], bf2[4][2];
#pragma unroll
                for (int mt = 0; mt < 4; mt++) {
                    uint32_t addr = ab + (uint32_t)(((wm + mt * 16 + (lane & 15)) * APITCH
                                                    + ks * 16 + (lane >> 4) * 8) << 1);
                    ldsm4(af[mt][0], af[mt][1], af[mt][2], af[mt][3], addr);
                }
#pragma unroll
                for (int nt = 0; nt < 4; nt++) {
                    uint32_t addr = bbse + (uint32_t)(((ks * 16 + (lane & 15)) * BPITCH
                                                      + wn + nt * 8) << 1);
                    ldsm2t(bf2[nt][0], bf2[nt][1], addr);
                }
#pragma unroll
                for (int mt = 0; mt < 4; mt++)
#pragma unroll
                    for (int nt = 0; nt < 4; nt++)
                        mma16816(acc[mt][nt], af[mt], bf2[nt]);
            }
        }
    }

    // epilogue: fragment rows lane/4 (+8), cols 2*(lane%4)+{0,1}
    const int gr = lane >> 2, gc = (lane & 3) * 2;
#pragma unroll
    for (int mt = 0; mt < 4; mt++) {
        const int row0 = bm + wm + mt * 16 + gr;
        float* p0 = Cd + (size_t)bb * CHWc + (size_t)row0 * HWc + n0 + wn;
        float* p1 = p0 + (size_t)8 * HWc;
        if (modeC == 0) {
#pragma unroll
            for (int nt = 0; nt < 4; nt++) {
                *(float2*)(p0 + nt * 8 + gc) = make_float2(acc[mt][nt][0], acc[mt][nt][1]);
                *(float2*)(p1 + nt * 8 + gc) = make_float2(acc[mt][nt][2], acc[mt][nt][3]);
            }
        } else {
            const float gb0 = gbias[row0], gb1 = gbias[row0 + 8];
#pragma unroll
            for (int nt = 0; nt < 4; nt++) {
                *(float2*)(p0 + nt * 8 + gc) =
                    make_float2(sigmoid_f(acc[mt][nt][0] + gb0), sigmoid_f(acc[mt][nt][1] + gb0));
                *(float2*)(p1 + nt * 8 + gc) =
                    make_float2(sigmoid_f(acc[mt][nt][2] + gb1), sigmoid_f(acc[mt][nt][3] + gb1));
            }
        }
    }
}

// ---------------- GroupNorm stats -> per-(b,c) affine ----------------
__global__ __launch_bounds__(1024) void gn_stats_kernel(const float* __restrict__ src,
                                                        const float* __restrict__ gamma,
                                                        const float* __restrict__ beta,
                                                        float* __restrict__ ss)
{
    const int g = blockIdx.x, b = blockIdx.y, tid = threadIdx.x;
    const float4* p = (const float4*)(src + (size_t)b * CHWc + (size_t)g * 16 * HWc);
    float s = 0.0f, s2 = 0.0f;
    const int n4 = 16 * HWc / 4;
    for (int i = tid; i < n4; i += 1024) {
        float4 v = p[i];
        s  += v.x + v.y + v.z + v.w;
        s2 += v.x * v.x + v.y * v.y + v.z * v.z + v.w * v.w;
    }
#pragma unroll
    for (int off = 16; off > 0; off >>= 1) {
        s  += __shfl_xor_sync(0xffffffffu, s, off);
        s2 += __shfl_xor_sync(0xffffffffu, s2, off);
    }
    __shared__ float ws[32], ws2[32];
    __shared__ float mean_s, rstd_s;
    const int wid = tid >> 5, lane = tid & 31;
    if (lane == 0) { ws[wid] = s; ws2[wid] = s2; }
    __syncthreads();
    if (tid < 32) {
        float ts = ws[tid], ts2 = ws2[tid];
#pragma unroll
        for (int off = 16; off > 0; off >>= 1) {
            ts  += __shfl_xor_sync(0xffffffffu, ts, off);
            ts2 += __shfl_xor_sync(0xffffffffu, ts2, off);
        }
        if (tid == 0) {
            const float inv = 1.0f / (16.0f * HWc);
            float mu  = ts * inv;
            float var = ts2 * inv - mu * mu;
            mean_s = mu;
            rstd_s = rsqrtf(var + 1e-5f);
        }
    }
    __syncthreads();
    if (tid < 16) {
        int c = g * 16 + tid;
        float sc = rstd_s * gamma[c];
        ss[(b * Cn + c) * 2 + 0] = sc;
        ss[(b * Cn + c) * 2 + 1] = beta[c] - mean_s * sc;
    }
}

// ---------------- horizontal scans: warp-per-row parallel scan ----------------
__global__ __launch_bounds__(256) void scan_w_kernel(const float* __restrict__ ap,
                                                     const float* __restrict__ bp,
                                                     const float* __restrict__ cp,
                                                     const float* __restrict__ dp)
{
    const int gw = blockIdx.x * 8 + (threadIdx.x >> 5);
    const int lane = threadIdx.x & 31;
    const int bc = gw / Hn;
    const int c  = bc & (Cn - 1);
    const float2 sc = *(const float2*)&g_ss1[bc * 2];
    const float a0 = sigmoid_f(ap[c]),    b0 = bp[c],    c0 = cp[c],    d0 = dp[c];
    const float a1 = sigmoid_f(ap[Cn+c]), b1 = bp[Cn+c], c1 = cp[Cn+c], d1 = dp[Cn+c];
    const float* xr = g_xp + (size_t)gw * Wn;

    float x0 = 0.f, x1 = 0.f, x2 = 0.f, x3 = 0.f;
    if (lane < 24) {
        float4 v = *(const float4*)(xr + lane * 4);
        x0 = silu_f(fmaf(v.x, sc.x, sc.y));
        x1 = silu_f(fmaf(v.y, sc.x, sc.y));
        x2 = silu_f(fmaf(v.z, sc.x, sc.y));
        x3 = silu_f(fmaf(v.w, sc.x, sc.y));
    }
    float a0_4 = (a0 * a0) * (a0 * a0);
    float S = b0 * x0;
    S = fmaf(a0, S, b0 * x1); S = fmaf(a0, S, b0 * x2); S = fmaf(a0, S, b0 * x3);
    float P = a0_4;
#pragma unroll
    for (int off = 1; off < 32; off <<= 1) {
        float Sp = __shfl_up_sync(0xffffffffu, S, off);
        float Pp = __shfl_up_sync(0xffffffffu, P, off);
        if (lane >= off) { S = fmaf(Sp, P, S); P *= Pp; }
    }
    float Hin = __shfl_up_sync(0xffffffffu, S, 1);
    if (lane == 0) Hin = 0.f;
    float hh = Hin;
    hh = fmaf(a0, hh, b0 * x0); float y0 = fmaf(c0, hh, d0 * x0);
    hh = fmaf(a0, hh, b0 * x1); float y1 = fmaf(c0, hh, d0 * x1);
    hh = fmaf(a0, hh, b0 * x2); float y2 = fmaf(c0, hh, d0 * x2);
    hh = fmaf(a0, hh, b0 * x3); float y3 = fmaf(c0, hh, d0 * x3);
    float a1_4 = (a1 * a1) * (a1 * a1);
    float S2 = b1 * x3;
    S2 = fmaf(a1, S2, b1 * x2); S2 = fmaf(a1, S2, b1 * x1); S2 = fmaf(a1, S2, b1 * x0);
    float P2 = a1_4;
    if (lane >= 24) { S2 = 0.f; P2 = 1.f; }
#pragma unroll
    for (int off = 1; off < 32; off <<= 1) {
        float Sp = __shfl_down_sync(0xffffffffu, S2, off);
        float Pp = __shfl_down_sync(0xffffffffu, P2, off);
        if (lane + off < 32) { S2 = fmaf(Sp, P2, S2); P2 *= Pp; }
    }
    float Hin2 = __shfl_down_sync(0xffffffffu, S2, 1);
    if (lane == 31) Hin2 = 0.f;
    hh = Hin2;
    hh = fmaf(a1, hh, b1 * x3); y3 += fmaf(c1, hh, d1 * x3);
    hh = fmaf(a1, hh, b1 * x2); y2 += fmaf(c1, hh, d1 * x2);
    hh = fmaf(a1, hh, b1 * x1); y1 += fmaf(c1, hh, d1 * x1);
    hh = fmaf(a1, hh, b1 * x0); y0 += fmaf(c1, hh, d1 * x0);

    if (lane < 24)
        *(float4*)(g_sw + (size_t)gw * Wn + lane * 4) = make_float4(y0, y1, y2, y3);
}

// ---------------- vertical scans: block per (b,c), thread per column ----------------
__global__ __launch_bounds__(96) void scan_h_kernel(const float* __restrict__ ap,
                                                    const float* __restrict__ bp,
                                                    const float* __restrict__ cp,
                                                    const float* __restrict__ dp)
{
    extern __shared__ float sh[];
    float* xin  = sh;
    float* ytmp = sh + HWc;
    const int bc = blockIdx.x;
    const int c  = bc & (Cn - 1);
    const int tid = threadIdx.x;
    const float2 sc = *(const float2*)&g_ss1[bc * 2];
    const size_t base = (size_t)bc * HWc;

    for (int i = tid; i < HWc; i += 96)
        xin[i] = silu_f(fmaf(g_xp[base + i], sc.x, sc.y));
    __syncthreads();

    const float a2 = sigmoid_f(ap[2*Cn+c]), b2 = bp[2*Cn+c], c2 = cp[2*Cn+c], d2 = dp[2*Cn+c];
    const float a3 = sigmoid_f(ap[3*Cn+c]), b3 = bp[3*Cn+c], c3 = cp[3*Cn+c], d3 = dp[3*Cn+c];
    const int w = tid;
    float hs = 0.f;
#pragma unroll 4
    for (int hhi = Hn - 1; hhi >= 0; hhi--) {
        float xv = xin[hhi * Wn + w];
        hs = fmaf(a3, hs, b3 * xv);
        ytmp[hhi * Wn + w] = fmaf(c3, hs, d3 * xv);
    }
    hs = 0.f;
#pragma unroll 4
    for (int hhi = 0; hhi < Hn; hhi++) {
        float xv = xin[hhi * Wn + w];
        hs = fmaf(a2, hs, b2 * xv);
        g_sh[base + hhi * Wn + w] = fmaf(c2, hs, d2 * xv) + ytmp[hhi * Wn + w];
    }
}

// ---------------- fused = 0.25*(sw+sh)*gate, 3x3 depthwise SAME conv ----------------
__global__ __launch_bounds__(256) void fuse_dw_kernel(const float* __restrict__ dww)
{
    __shared__ float ft[34 * 36];
    const int bc = blockIdx.z;
    const int h0 = blockIdx.y * 32, w0 = blockIdx.x * 32;
    const int c = bc & (Cn - 1);
    const size_t base = (size_t)bc * HWc;
    const int tid = threadIdx.x;

    for (int i = tid; i < 34 * 34; i += 256) {
        int r = i / 34, cc = i - r * 34;
        int gh = h0 - 1 + r, gw = w0 - 1 + cc;
        float v = 0.0f;
        if ((unsigned)gh < (unsigned)Hn && (unsigned)gw < (unsigned)Wn) {
            size_t idx = base + gh * Wn + gw;
            v = 0.25f * (g_sw[idx] + g_sh[idx]) * g_gate[idx];
        }
        ft[r * 36 + cc] = v;
    }
    float kw[9];
#pragma unroll
    for (int j = 0; j < 9; j++) kw[j] = dww[c * 9 + j];
    __syncthreads();

    const int tx = tid & 31, ty0 = tid >> 5;
#pragma unroll
    for (int rr = 0; rr < 4; rr++) {
        int r = ty0 + rr * 8;
        float acc = 0.0f;
#pragma unroll
        for (int i = 0; i < 3; i++)
#pragma unroll
            for (int j = 0; j < 3; j++)
                acc = fmaf(ft[(r + i) * 36 + tx + j], kw[i * 3 + j], acc);
        g_fd[base + (size_t)(h0 + r) * Wn + w0 + tx] = acc;
    }
}

// ---------------- final: silu(affine(o1)) -> out ----------------
__global__ __launch_bounds__(256) void finalize_kernel(const float* __restrict__ src,
                                                       const float* __restrict__ ss,
                                                       float* __restrict__ out)
{
    int i4 = blockIdx.x * 256 + threadIdx.x;
    if (i4 >= TOTc / 4) return;
    int bc = i4 / (HWc / 4);
    float2 sc = *(const float2*)&ss[bc * 2];
    float4 v = ((const float4*)src)[i4];
    v.x = silu_f(fmaf(v.x, sc.x, sc.y));
    v.y = silu_f(fmaf(v.y, sc.x, sc.y));
    v.z = silu_f(fmaf(v.z, sc.x, sc.y));
    v.w = silu_f(fmaf(v.w, sc.x, sc.y));
    ((float4*)out)[i4] = v;
}

// ---------------- launch ----------------
extern "C" void kernel_launch(void* const* d_in, const int* in_sizes, int n_in,
                              void* d_out, int out_size)
{
    const float* x      = (const float*)d_in[0];
    const float* in_w   = (const float*)d_in[1];
    const float* gn1_w  = (const float*)d_in[2];
    const float* gn1_b  = (const float*)d_in[3];
    const float* a_p    = (const float*)d_in[4];
    const float* b_p    = (const float*)d_in[5];
    const float* c_p    = (const float*)d_in[6];
    const float* d_p    = (const float*)d_in[7];
    const float* gate_w = (const float*)d_in[8];
    const float* gate_b = (const float*)d_in[9];
    const float* dw_w   = (const float*)d_in[10];
    const float* pw_w   = (const float*)d_in[11];
    const float* gn2_w  = (const float*)d_in[12];
    const float* gn2_b  = (const float*)d_in[13];
    float* out = (float*)d_out;

    float *p_xp, *p_gate, *p_fd, *p_o1, *p_ss1, *p_ss2;
    cudaGetSymbolAddress((void**)&p_xp,   g_xp);
    cudaGetSymbolAddress((void**)&p_gate, g_gate);
    cudaGetSymbolAddress((void**)&p_fd,   g_fd);
    cudaGetSymbolAddress((void**)&p_o1,   g_o1);
    cudaGetSymbolAddress((void**)&p_ss1,  g_ss1);
    cudaGetSymbolAddress((void**)&p_ss2,  g_ss2);

    const int smh = 2 * HWc * 4;
    cudaFuncSetAttribute(scan_h_kernel, cudaFuncAttributeMaxDynamicSharedMemorySize, smh);
    cudaFuncSetAttribute(gemm_fused_kernel, cudaFuncAttributeMaxDynamicSharedMemorySize, GSM_TOT);

    dim3 gmm(HWc / 128, Cn / 128, Bn);

    // GEMM1: xp = in_w @ x
    gemm_fused_kernel<<<gmm, 256, GSM_TOT>>>(in_w, x, p_xp, p_ss1, gate_b, 0, 0);
    gn_stats_kernel<<<dim3(16, Bn), 1024>>>(p_xp, gn1_w, gn1_b, p_ss1);

    // gate GEMM: gate = sigmoid(gate_w @ silu(affine(xp)) + b)
    gemm_fused_kernel<<<gmm, 256, GSM_TOT>>>(gate_w, p_xp, p_gate, p_ss1, gate_b, 1, 1);

    // scans + fuse + depthwise
    scan_w_kernel<<<Bn * Cn * Hn / 8, 256>>>(a_p, b_p, c_p, d_p);
    scan_h_kernel<<<Bn * Cn, 96, smh>>>(a_p, b_p, c_p, d_p);
    fuse_dw_kernel<<<dim3(3, 3, Bn * Cn), 256>>>(dw_w);

    // GEMM3: o1 = pw_w @ fd
    gemm_fused_kernel<<<gmm, 256, GSM_TOT>>>(pw_w, p_fd, p_o1, p_ss1, gate_b, 0, 0);

    gn_stats_kernel<<<dim3(16, Bn), 1024>>>(p_o1, gn2_w, gn2_b, p_ss2);
    finalize_kernel<<<(TOTc / 4 + 255) / 256, 256>>>(p_o1, p_ss2, out);
}

// round 11
// speedup vs baseline: 1.0805x; 1.0805x over previous
#include <cuda_runtime.h>
#include <cuda_bf16.h>
#include <cstdint>

#define Bn 16
#define Cn 256
#define Hn 96
#define Wn 96
#define HWc 9216
#define CHWc 2359296   // Cn*HWc
#define TOTc 37748736  // Bn*CHWc

// ---------------- scratch ----------------
__device__ float g_xp[TOTc];
__device__ float g_gate[TOTc];
__device__ float g_sw[TOTc];
__device__ float g_sh[TOTc];
__device__ float g_fd[TOTc];
__device__ float g_o1[TOTc];
__device__ float g_ss1[Bn*Cn*2];
__device__ float g_ss2[Bn*Cn*2];
__device__ __nv_bfloat16 g_bth[TOTc];   // B transposed [b][n][k], hi
__device__ __nv_bfloat16 g_btl[TOTc];   // lo
__device__ __nv_bfloat16 g_ahh[Cn*Cn];  // A hi
__device__ __nv_bfloat16 g_all[Cn*Cn];  // A lo

__device__ __forceinline__ float sigmoid_f(float x) { return 1.0f / (1.0f + __expf(-x)); }
__device__ __forceinline__ float silu_f(float x)    { return x / (1.0f + __expf(-x)); }

__device__ __forceinline__ uint32_t smem_u32(const void* p) {
    uint32_t a;
    asm("{ .reg .u64 t; cvta.to.shared.u64 t, %1; cvt.u32.u64 %0, t; }" : "=r"(a) : "l"(p));
    return a;
}
__device__ __forceinline__ void ldsm4(uint32_t &r0, uint32_t &r1, uint32_t &r2, uint32_t &r3, uint32_t addr) {
    asm volatile("ldmatrix.sync.aligned.m8n8.x4.shared.b16 {%0,%1,%2,%3}, [%4];"
                 : "=r"(r0), "=r"(r1), "=r"(r2), "=r"(r3) : "r"(addr));
}
__device__ __forceinline__ void ldsm2(uint32_t &r0, uint32_t &r1, uint32_t addr) {
    asm volatile("ldmatrix.sync.aligned.m8n8.x2.shared.b16 {%0,%1}, [%2];"
                 : "=r"(r0), "=r"(r1) : "r"(addr));
}
__device__ __forceinline__ void mma16816(float* d, const uint32_t* a, const uint32_t* b) {
    asm volatile("mma.sync.aligned.m16n8k16.row.col.f32.bf16.bf16.f32 "
                 "{%0,%1,%2,%3}, {%4,%5,%6,%7}, {%8,%9}, {%0,%1,%2,%3};"
                 : "+f"(d[0]), "+f"(d[1]), "+f"(d[2]), "+f"(d[3])
                 : "r"(a[0]), "r"(a[1]), "r"(a[2]), "r"(a[3]), "r"(b[0]), "r"(b[1]));
}
__device__ __forceinline__ void cpa16(uint32_t sm, const void* g) {
    asm volatile("cp.async.cg.shared.global [%0], [%1], 16;" :: "r"(sm), "l"(g));
}
#define CPA_COMMIT() asm volatile("cp.async.commit_group;" ::: "memory")
#define CPA_WAIT1()  asm volatile("cp.async.wait_group 1;" ::: "memory")
#define CPA_WAIT0()  asm volatile("cp.async.wait_group 0;" ::: "memory")

// ================ conversion kernels ================
__global__ __launch_bounds__(256) void convA_kernel(const float* __restrict__ A,
                                                    __nv_bfloat16* __restrict__ ah,
                                                    __nv_bfloat16* __restrict__ al)
{
    int i = blockIdx.x * 256 + threadIdx.x;
    float v = A[i];
    __nv_bfloat16 h = __float2bfloat16(v);
    ah[i] = h;
    al[i] = __float2bfloat16(v - __bfloat162float(h));
}

// src fp32 [b][K=256][N=9216] -> bh/bl bf16 [b][N=9216][K=256]; mode1: silu(affine) via ss
__global__ __launch_bounds__(256) void convT_kernel(const float* __restrict__ src,
                                                    __nv_bfloat16* __restrict__ bh,
                                                    __nv_bfloat16* __restrict__ bl,
                                                    const float* __restrict__ ss, int mode)
{
    __shared__ float t[32][33];
    const int n0 = blockIdx.x * 32, k0 = blockIdx.y * 32, bb = blockIdx.z;
    const int tx = threadIdx.x, ty = threadIdx.y;
#pragma unroll
    for (int i = 0; i < 4; i++) {
        int k = k0 + ty + 8 * i;
        float v = src[(size_t)bb * CHWc + (size_t)k * HWc + n0 + tx];
        if (mode) {
            float2 sc = *(const float2*)&ss[(bb * Cn + k) * 2];
            v = silu_f(fmaf(v, sc.x, sc.y));
        }
        t[ty + 8 * i][tx] = v;
    }
    __syncthreads();
#pragma unroll
    for (int i = 0; i < 4; i++) {
        int n = n0 + ty + 8 * i;
        float v = t[tx][ty + 8 * i];
        __nv_bfloat16 h = __float2bfloat16(v);
        size_t o = (size_t)bb * CHWc + (size_t)n * Cn + k0 + tx;
        bh[o] = h;
        bl[o] = __float2bfloat16(v - __bfloat162float(h));
    }
}

// ================ bf16 warp-MMA GEMM: C[b][m][n] = sum_k A[m][k]*Bt[b][n][k] ================
// BM=256 (full M), BN=128, BK=32. 512 threads = 16 warps (4m x 4n), warp tile 64x32.
// 24 iters = 3 split passes x 8 k-steps: (Ah,Bh), (Al,Bh), (Ah,Bl).
// cp.async 3-stage pipeline, depth-2 prefetch.
#define PITCH 40            // bf16/row: 80B stride, conflict-free ldmatrix
#define STG_A (256 * PITCH * 2)             // 20480
#define STG_B (128 * PITCH * 2)             // 10240
#define STG_SZ (STG_A + STG_B)              // 30720
#define GSM_TOT (3 * STG_SZ)                // 92160

__global__ __launch_bounds__(512) void gemm_mma_kernel(
    const __nv_bfloat16* __restrict__ Ah, const __nv_bfloat16* __restrict__ Al,
    const __nv_bfloat16* __restrict__ Bh, const __nv_bfloat16* __restrict__ Bl,
    float* __restrict__ Cd, const float* __restrict__ gbias, int mode)
{
    extern __shared__ __align__(16) char gsm[];
    const uint32_t su = smem_u32(gsm);
    const int tid = threadIdx.x, lane = tid & 31, warp = tid >> 5;
    const int wm = (warp & 3) * 64, wn = (warp >> 2) * 32;
    const int n0 = blockIdx.x * 128, bb = blockIdx.z;

    const __nv_bfloat16* Apass[3] = {Ah, Al, Ah};
    const __nv_bfloat16* Bpass[3] = {Bh, Bh, Bl};

    // cp.async staging indices
    const int a_r = tid >> 1, a_c = (tid & 1) * 16;   // A: 256 rows, 2x16B per thread
    const int b_n = tid >> 2, b_c = (tid & 3) * 8;    // B: 128 rows, 1x16B per thread
    const size_t bbase = (size_t)bb * HWc + n0;

    float acc[4][4][4];
#pragma unroll
    for (int i = 0; i < 4; i++)
#pragma unroll
        for (int j = 0; j < 4; j++)
#pragma unroll
            for (int k = 0; k < 4; k++) acc[i][j][k] = 0.0f;

    // ---- prologue: load stages for it=0,1
#pragma unroll
    for (int pre = 0; pre < 2; pre++) {
        const int p = 0, k0 = pre * 32;
        const uint32_t sb = su + pre * STG_SZ;
        cpa16(sb + (uint32_t)((a_r * PITCH + a_c) << 1),
              Apass[p] + (size_t)a_r * 256 + k0 + a_c);
        cpa16(sb + (uint32_t)((a_r * PITCH + a_c + 8) << 1),
              Apass[p] + (size_t)a_r * 256 + k0 + a_c + 8);
        cpa16(sb + STG_A + (uint32_t)((b_n * PITCH + b_c) << 1),
              Bpass[p] + (bbase + b_n) * 256 + k0 + b_c);
        CPA_COMMIT();
    }

    int stage = 0;
    for (int it = 0; it < 24; it++) {
        if (it < 23) CPA_WAIT1(); else CPA_WAIT0();
        __syncthreads();
        // issue load for it+2 into stage (it+2)%3 (computed at it-1; safe after barrier)
        if (it < 22) {
            const int nx = it + 2, p = nx >> 3, k0 = (nx & 7) * 32;
            int s2 = stage + 2; if (s2 >= 3) s2 -= 3;
            const uint32_t sb = su + s2 * STG_SZ;
            cpa16(sb + (uint32_t)((a_r * PITCH + a_c) << 1),
                  Apass[p] + (size_t)a_r * 256 + k0 + a_c);
            cpa16(sb + (uint32_t)((a_r * PITCH + a_c + 8) << 1),
                  Apass[p] + (size_t)a_r * 256 + k0 + a_c + 8);
            cpa16(sb + STG_A + (uint32_t)((b_n * PITCH + b_c) << 1),
                  Bpass[p] + (bbase + b_n) * 256 + k0 + b_c);
            CPA_COMMIT();
        }
        const uint32_t sa = su + stage * STG_SZ;
        const uint32_t sb = sa + STG_A;
#pragma unroll
        for (int ks = 0; ks < 2; ks++) {
            uint32_t af[4][4], bf2[4][2];
#pragma unroll
            for (int mt = 0; mt < 4; mt++) {
                uint32_t addr = sa + (uint32_t)(((wm + mt * 16 + (lane & 15)) * PITCH
                                                + ks * 16 + (lane >> 4) * 8) << 1);
                ldsm4(af[mt][0], af[mt][1], af[mt][2], af[mt][3], addr);
            }
#pragma unroll
            for (int nt = 0; nt < 4; nt++) {
                uint32_t addr = sb + (uint32_t)(((wn + nt * 8 + (lane & 7)) * PITCH
                                                + ks * 16 + ((lane >> 3) & 1) * 8) << 1);
                ldsm2(bf2[nt][0], bf2[nt][1], addr);
            }
#pragma unroll
            for (int mt = 0; mt < 4; mt++)
#pragma unroll
                for (int nt = 0; nt < 4; nt++)
                    mma16816(acc[mt][nt], af[mt], bf2[nt]);
        }
        if (++stage == 3) stage = 0;
    }

    // epilogue: fragment rows lane/4 (+8), cols 2*(lane%4)+{0,1}
    const int gr = lane >> 2, gc = (lane & 3) * 2;
#pragma unroll
    for (int mt = 0; mt < 4; mt++) {
        const int row0 = wm + mt * 16 + gr;
        float* p0 = Cd + (size_t)bb * CHWc + (size_t)row0 * HWc + n0 + wn;
        float* p1 = p0 + (size_t)8 * HWc;
        if (mode == 0) {
#pragma unroll
            for (int nt = 0; nt < 4; nt++) {
                *(float2*)(p0 + nt * 8 + gc) = make_float2(acc[mt][nt][0], acc[mt][nt][1]);
                *(float2*)(p1 + nt * 8 + gc) = make_float2(acc[mt][nt][2], acc[mt][nt][3]);
            }
        } else {
            const float gb0 = gbias[row0], gb1 = gbias[row0 + 8];
#pragma unroll
            for (int nt = 0; nt < 4; nt++) {
                *(float2*)(p0 + nt * 8 + gc) =
                    make_float2(sigmoid_f(acc[mt][nt][0] + gb0), sigmoid_f(acc[mt][nt][1] + gb0));
                *(float2*)(p1 + nt * 8 + gc) =
                    make_float2(sigmoid_f(acc[mt][nt][2] + gb1), sigmoid_f(acc[mt][nt][3] + gb1));
            }
        }
    }
}

// ---------------- GroupNorm stats -> per-(b,c) affine ----------------
__global__ __launch_bounds__(1024) void gn_stats_kernel(const float* __restrict__ src,
                                                        const float* __restrict__ gamma,
                                                        const float* __restrict__ beta,
                                                        float* __restrict__ ss)
{
    const int g = blockIdx.x, b = blockIdx.y, tid = threadIdx.x;
    const float4* p = (const float4*)(src + (size_t)b * CHWc + (size_t)g * 16 * HWc);
    float s = 0.0f, s2 = 0.0f;
    const int n4 = 16 * HWc / 4;
    for (int i = tid; i < n4; i += 1024) {
        float4 v = p[i];
        s  += v.x + v.y + v.z + v.w;
        s2 += v.x * v.x + v.y * v.y + v.z * v.z + v.w * v.w;
    }
#pragma unroll
    for (int off = 16; off > 0; off >>= 1) {
        s  += __shfl_xor_sync(0xffffffffu, s, off);
        s2 += __shfl_xor_sync(0xffffffffu, s2, off);
    }
    __shared__ float ws[32], ws2[32];
    __shared__ float mean_s, rstd_s;
    const int wid = tid >> 5, lane = tid & 31;
    if (lane == 0) { ws[wid] = s; ws2[wid] = s2; }
    __syncthreads();
    if (tid < 32) {
        float ts = ws[tid], ts2 = ws2[tid];
#pragma unroll
        for (int off = 16; off > 0; off >>= 1) {
            ts  += __shfl_xor_sync(0xffffffffu, ts, off);
            ts2 += __shfl_xor_sync(0xffffffffu, ts2, off);
        }
        if (tid == 0) {
            const float inv = 1.0f / (16.0f * HWc);
            float mu  = ts * inv;
            float var = ts2 * inv - mu * mu;
            mean_s = mu;
            rstd_s = rsqrtf(var + 1e-5f);
        }
    }
    __syncthreads();
    if (tid < 16) {
        int c = g * 16 + tid;
        float sc = rstd_s * gamma[c];
        ss[(b * Cn + c) * 2 + 0] = sc;
        ss[(b * Cn + c) * 2 + 1] = beta[c] - mean_s * sc;
    }
}

// ---------------- horizontal scans: warp-per-row parallel scan ----------------
__global__ __launch_bounds__(256) void scan_w_kernel(const float* __restrict__ ap,
                                                     const float* __restrict__ bp,
                                                     const float* __restrict__ cp,
                                                     const float* __restrict__ dp)
{
    const int gw = blockIdx.x * 8 + (threadIdx.x >> 5);
    const int lane = threadIdx.x & 31;
    const int bc = gw / Hn;
    const int c  = bc & (Cn - 1);
    const float2 sc = *(const float2*)&g_ss1[bc * 2];
    const float a0 = sigmoid_f(ap[c]),    b0 = bp[c],    c0 = cp[c],    d0 = dp[c];
    const float a1 = sigmoid_f(ap[Cn+c]), b1 = bp[Cn+c], c1 = cp[Cn+c], d1 = dp[Cn+c];
    const float* xr = g_xp + (size_t)gw * Wn;

    float x0 = 0.f, x1 = 0.f, x2 = 0.f, x3 = 0.f;
    if (lane < 24) {
        float4 v = *(const float4*)(xr + lane * 4);
        x0 = silu_f(fmaf(v.x, sc.x, sc.y));
        x1 = silu_f(fmaf(v.y, sc.x, sc.y));
        x2 = silu_f(fmaf(v.z, sc.x, sc.y));
        x3 = silu_f(fmaf(v.w, sc.x, sc.y));
    }
    float a0_4 = (a0 * a0) * (a0 * a0);
    float S = b0 * x0;
    S = fmaf(a0, S, b0 * x1); S = fmaf(a0, S, b0 * x2); S = fmaf(a0, S, b0 * x3);
    float P = a0_4;
#pragma unroll
    for (int off = 1; off < 32; off <<= 1) {
        float Sp = __shfl_up_sync(0xffffffffu, S, off);
        float Pp = __shfl_up_sync(0xffffffffu, P, off);
        if (lane >= off) { S = fmaf(Sp, P, S); P *= Pp; }
    }
    float Hin = __shfl_up_sync(0xffffffffu, S, 1);
    if (lane == 0) Hin = 0.f;
    float hh = Hin;
    hh = fmaf(a0, hh, b0 * x0); float y0 = fmaf(c0, hh, d0 * x0);
    hh = fmaf(a0, hh, b0 * x1); float y1 = fmaf(c0, hh, d0 * x1);
    hh = fmaf(a0, hh, b0 * x2); float y2 = fmaf(c0, hh, d0 * x2);
    hh = fmaf(a0, hh, b0 * x3); float y3 = fmaf(c0, hh, d0 * x3);
    float a1_4 = (a1 * a1) * (a1 * a1);
    float S2 = b1 * x3;
    S2 = fmaf(a1, S2, b1 * x2); S2 = fmaf(a1, S2, b1 * x1); S2 = fmaf(a1, S2, b1 * x0);
    float P2 = a1_4;
    if (lane >= 24) { S2 = 0.f; P2 = 1.f; }
#pragma unroll
    for (int off = 1; off < 32; off <<= 1) {
        float Sp = __shfl_down_sync(0xffffffffu, S2, off);
        float Pp = __shfl_down_sync(0xffffffffu, P2, off);
        if (lane + off < 32) { S2 = fmaf(Sp, P2, S2); P2 *= Pp; }
    }
    float Hin2 = __shfl_down_sync(0xffffffffu, S2, 1);
    if (lane == 31) Hin2 = 0.f;
    hh = Hin2;
    hh = fmaf(a1, hh, b1 * x3); y3 += fmaf(c1, hh, d1 * x3);
    hh = fmaf(a1, hh, b1 * x2); y2 += fmaf(c1, hh, d1 * x2);
    hh = fmaf(a1, hh, b1 * x1); y1 += fmaf(c1, hh, d1 * x1);
    hh = fmaf(a1, hh, b1 * x0); y0 += fmaf(c1, hh, d1 * x0);

    if (lane < 24)
        *(float4*)(g_sw + (size_t)gw * Wn + lane * 4) = make_float4(y0, y1, y2, y3);
}

// ---------------- vertical scans: block per (b,c), thread per column ----------------
__global__ __launch_bounds__(96) void scan_h_kernel(const float* __restrict__ ap,
                                                    const float* __restrict__ bp,
                                                    const float* __restrict__ cp,
                                                    const float* __restrict__ dp)
{
    extern __shared__ float sh[];
    float* xin  = sh;
    float* ytmp = sh + HWc;
    const int bc = blockIdx.x;
    const int c  = bc & (Cn - 1);
    const int tid = threadIdx.x;
    const float2 sc = *(const float2*)&g_ss1[bc * 2];
    const size_t base = (size_t)bc * HWc;

    for (int i = tid; i < HWc; i += 96)
        xin[i] = silu_f(fmaf(g_xp[base + i], sc.x, sc.y));
    __syncthreads();

    const float a2 = sigmoid_f(ap[2*Cn+c]), b2 = bp[2*Cn+c], c2 = cp[2*Cn+c], d2 = dp[2*Cn+c];
    const float a3 = sigmoid_f(ap[3*Cn+c]), b3 = bp[3*Cn+c], c3 = cp[3*Cn+c], d3 = dp[3*Cn+c];
    const int w = tid;
    float hs = 0.f;
#pragma unroll 4
    for (int hhi = Hn - 1; hhi >= 0; hhi--) {
        float xv = xin[hhi * Wn + w];
        hs = fmaf(a3, hs, b3 * xv);
        ytmp[hhi * Wn + w] = fmaf(c3, hs, d3 * xv);
    }
    hs = 0.f;
#pragma unroll 4
    for (int hhi = 0; hhi < Hn; hhi++) {
        float xv = xin[hhi * Wn + w];
        hs = fmaf(a2, hs, b2 * xv);
        g_sh[base + hhi * Wn + w] = fmaf(c2, hs, d2 * xv) + ytmp[hhi * Wn + w];
    }
}

// ---------------- fused = 0.25*(sw+sh)*gate, 3x3 depthwise SAME conv ----------------
__global__ __launch_bounds__(256) void fuse_dw_kernel(const float* __restrict__ dww)
{
    __shared__ float ft[34 * 36];
    const int bc = blockIdx.z;
    const int h0 = blockIdx.y * 32, w0 = blockIdx.x * 32;
    const int c = bc & (Cn - 1);
    const size_t base = (size_t)bc * HWc;
    const int tid = threadIdx.x;

    for (int i = tid; i < 34 * 34; i += 256) {
        int r = i / 34, cc = i - r * 34;
        int gh = h0 - 1 + r, gw = w0 - 1 + cc;
        float v = 0.0f;
        if ((unsigned)gh < (unsigned)Hn && (unsigned)gw < (unsigned)Wn) {
            size_t idx = base + gh * Wn + gw;
            v = 0.25f * (g_sw[idx] + g_sh[idx]) * g_gate[idx];
        }
        ft[r * 36 + cc] = v;
    }
    float kw[9];
#pragma unroll
    for (int j = 0; j < 9; j++) kw[j] = dww[c * 9 + j];
    __syncthreads();

    const int tx = tid & 31, ty0 = tid >> 5;
#pragma unroll
    for (int rr = 0; rr < 4; rr++) {
        int r = ty0 + rr * 8;
        float acc = 0.0f;
#pragma unroll
        for (int i = 0; i < 3; i++)
#pragma unroll
            for (int j = 0; j < 3; j++)
                acc = fmaf(ft[(r + i) * 36 + tx + j], kw[i * 3 + j], acc);
        g_fd[base + (size_t)(h0 + r) * Wn + w0 + tx] = acc;
    }
}

// ---------------- final: silu(affine(o1)) -> out ----------------
__global__ __launch_bounds__(256) void finalize_kernel(const float* __restrict__ src,
                                                       const float* __restrict__ ss,
                                                       float* __restrict__ out)
{
    int i4 = blockIdx.x * 256 + threadIdx.x;
    if (i4 >= TOTc / 4) return;
    int bc = i4 / (HWc / 4);
    float2 sc = *(const float2*)&ss[bc * 2];
    float4 v = ((const float4*)src)[i4];
    v.x = silu_f(fmaf(v.x, sc.x, sc.y));
    v.y = silu_f(fmaf(v.y, sc.x, sc.y));
    v.z = silu_f(fmaf(v.z, sc.x, sc.y));
    v.w = silu_f(fmaf(v.w, sc.x, sc.y));
    ((float4*)out)[i4] = v;
}

// ---------------- launch ----------------
extern "C" void kernel_launch(void* const* d_in, const int* in_sizes, int n_in,
                              void* d_out, int out_size)
{
    const float* x      = (const float*)d_in[0];
    const float* in_w   = (const float*)d_in[1];
    const float* gn1_w  = (const float*)d_in[2];
    const float* gn1_b  = (const float*)d_in[3];
    const float* a_p    = (const float*)d_in[4];
    const float* b_p    = (const float*)d_in[5];
    const float* c_p    = (const float*)d_in[6];
    const float* d_p    = (const float*)d_in[7];
    const float* gate_w = (const float*)d_in[8];
    const float* gate_b = (const float*)d_in[9];
    const float* dw_w   = (const float*)d_in[10];
    const float* pw_w   = (const float*)d_in[11];
    const float* gn2_w  = (const float*)d_in[12];
    const float* gn2_b  = (const float*)d_in[13];
    float* out = (float*)d_out;

    float *p_xp, *p_gate, *p_fd, *p_o1, *p_ss1, *p_ss2;
    __nv_bfloat16 *p_bth, *p_btl, *p_ah, *p_al;
    cudaGetSymbolAddress((void**)&p_xp,   g_xp);
    cudaGetSymbolAddress((void**)&p_gate, g_gate);
    cudaGetSymbolAddress((void**)&p_fd,   g_fd);
    cudaGetSymbolAddress((void**)&p_o1,   g_o1);
    cudaGetSymbolAddress((void**)&p_ss1,  g_ss1);
    cudaGetSymbolAddress((void**)&p_ss2,  g_ss2);
    cudaGetSymbolAddress((void**)&p_bth,  g_bth);
    cudaGetSymbolAddress((void**)&p_btl,  g_btl);
    cudaGetSymbolAddress((void**)&p_ah,   g_ahh);
    cudaGetSymbolAddress((void**)&p_al,   g_all);

    const int smh = 2 * HWc * 4;
    cudaFuncSetAttribute(scan_h_kernel, cudaFuncAttributeMaxDynamicSharedMemorySize, smh);
    cudaFuncSetAttribute(gemm_mma_kernel, cudaFuncAttributeMaxDynamicSharedMemorySize, GSM_TOT);

    dim3 gcv(HWc / 32, Cn / 32, Bn);
    dim3 bcv(32, 8);
    dim3 gmm(HWc / 128, 1, Bn);

    // GEMM1: xp = in_w @ x
    convT_kernel<<<gcv, bcv>>>(x, p_bth, p_btl, p_ss1, 0);
    convA_kernel<<<Cn * Cn / 256, 256>>>(in_w, p_ah, p_al);
    gemm_mma_kernel<<<gmm, 512, GSM_TOT>>>(p_ah, p_al, p_bth, p_btl, p_xp, gate_b, 0);
    gn_stats_kernel<<<dim3(16, Bn), 1024>>>(p_xp, gn1_w, gn1_b, p_ss1);

    // gate GEMM: gate = sigmoid(gate_w @ silu(affine(xp)) + b)
    convT_kernel<<<gcv, bcv>>>(p_xp, p_bth, p_btl, p_ss1, 1);
    convA_kernel<<<Cn * Cn / 256, 256>>>(gate_w, p_ah, p_al);
    gemm_mma_kernel<<<gmm, 512, GSM_TOT>>>(p_ah, p_al, p_bth, p_btl, p_gate, gate_b, 1);

    // scans + fuse + depthwise
    scan_w_kernel<<<Bn * Cn * Hn / 8, 256>>>(a_p, b_p, c_p, d_p);
    scan_h_kernel<<<Bn * Cn, 96, smh>>>(a_p, b_p, c_p, d_p);
    fuse_dw_kernel<<<dim3(3, 3, Bn * Cn), 256>>>(dw_w);

    // GEMM3: o1 = pw_w @ fd
    convT_kernel<<<gcv, bcv>>>(p_fd, p_bth, p_btl, p_ss1, 0);
    convA_kernel<<<Cn * Cn / 256, 256>>>(pw_w, p_ah, p_al);
    gemm_mma_kernel<<<gmm, 512, GSM_TOT>>>(p_ah, p_al, p_bth, p_btl, p_o1, gate_b, 0);

    gn_stats_kernel<<<dim3(16, Bn), 1024>>>(p_o1, gn2_w, gn2_b, p_ss2);
    finalize_kernel<<<(TOTc / 4 + 255) / 256, 256>>>(p_o1, p_ss2, out);
}

// round 12
// speedup vs baseline: 1.2102x; 1.1201x over previous
#include <cuda_runtime.h>
#include <cuda_bf16.h>
#include <cstdint>

#define Bn 16
#define Cn 256
#define Hn 96
#define Wn 96
#define HWc 9216
#define CHWc 2359296   // Cn*HWc
#define TOTc 37748736  // Bn*CHWc

// ---------------- scratch ----------------
__device__ float g_xp[TOTc];
__device__ float g_gate[TOTc];
__device__ float g_sw[TOTc];
__device__ float g_sh[TOTc];
__device__ float g_fd[TOTc];
__device__ float g_o1[TOTc];
__device__ float g_ss1[Bn*Cn*2];
__device__ float g_ss2[Bn*Cn*2];
__device__ __nv_bfloat16 g_bth[TOTc];       // B transposed [b][n][k], hi
__device__ __nv_bfloat16 g_btl[TOTc];       // lo
__device__ __nv_bfloat16 g_ahh[3*Cn*Cn];    // A hi (in_w, gate_w, pw_w)
__device__ __nv_bfloat16 g_all[3*Cn*Cn];    // A lo

__device__ __forceinline__ float sigmoid_f(float x) { return 1.0f / (1.0f + __expf(-x)); }
__device__ __forceinline__ float silu_f(float x)    { return x / (1.0f + __expf(-x)); }

__device__ __forceinline__ uint32_t smem_u32(const void* p) {
    uint32_t a;
    asm("{ .reg .u64 t; cvta.to.shared.u64 t, %1; cvt.u32.u64 %0, t; }" : "=r"(a) : "l"(p));
    return a;
}
__device__ __forceinline__ void ldsm4(uint32_t &r0, uint32_t &r1, uint32_t &r2, uint32_t &r3, uint32_t addr) {
    asm volatile("ldmatrix.sync.aligned.m8n8.x4.shared.b16 {%0,%1,%2,%3}, [%4];"
                 : "=r"(r0), "=r"(r1), "=r"(r2), "=r"(r3) : "r"(addr));
}
__device__ __forceinline__ void ldsm2(uint32_t &r0, uint32_t &r1, uint32_t addr) {
    asm volatile("ldmatrix.sync.aligned.m8n8.x2.shared.b16 {%0,%1}, [%2];"
                 : "=r"(r0), "=r"(r1) : "r"(addr));
}
__device__ __forceinline__ void mma16816(float* d, const uint32_t* a, const uint32_t* b) {
    asm volatile("mma.sync.aligned.m16n8k16.row.col.f32.bf16.bf16.f32 "
                 "{%0,%1,%2,%3}, {%4,%5,%6,%7}, {%8,%9}, {%0,%1,%2,%3};"
                 : "+f"(d[0]), "+f"(d[1]), "+f"(d[2]), "+f"(d[3])
                 : "r"(a[0]), "r"(a[1]), "r"(a[2]), "r"(a[3]), "r"(b[0]), "r"(b[1]));
}
__device__ __forceinline__ void cpa16(uint32_t sm, const void* g) {
    asm volatile("cp.async.cg.shared.global [%0], [%1], 16;" :: "r"(sm), "l"(g));
}
#define CPA_COMMIT() asm volatile("cp.async.commit_group;" ::: "memory")
#define CPA_WAIT1()  asm volatile("cp.async.wait_group 1;" ::: "memory")
#define CPA_WAIT0()  asm volatile("cp.async.wait_group 0;" ::: "memory")

// ================ conversion kernels ================
// all three A matrices at once: in_w, gate_w, pw_w
__global__ __launch_bounds__(256) void convA3_kernel(const float* __restrict__ w0,
                                                     const float* __restrict__ w1,
                                                     const float* __restrict__ w2,
                                                     __nv_bfloat16* __restrict__ ah,
                                                     __nv_bfloat16* __restrict__ al)
{
    int i = blockIdx.x * 256 + threadIdx.x;
    int which = i >> 16, j = i & 65535;
    const float* s = (which == 0) ? w0 : ((which == 1) ? w1 : w2);
    float v = s[j];
    __nv_bfloat16 h = __float2bfloat16(v);
    ah[i] = h;
    al[i] = __float2bfloat16(v - __bfloat162float(h));
}

// src fp32 [b][K=256][N=9216] -> bh/bl bf16 [b][N=9216][K=256]; mode1: silu(affine) via ss
__global__ __launch_bounds__(256) void convT_kernel(const float* __restrict__ src,
                                                    __nv_bfloat16* __restrict__ bh,
                                                    __nv_bfloat16* __restrict__ bl,
                                                    const float* __restrict__ ss, int mode)
{
    __shared__ float t[32][33];
    const int n0 = blockIdx.x * 32, k0 = blockIdx.y * 32, bb = blockIdx.z;
    const int tx = threadIdx.x, ty = threadIdx.y;
#pragma unroll
    for (int i = 0; i < 4; i++) {
        int k = k0 + ty + 8 * i;
        float v = src[(size_t)bb * CHWc + (size_t)k * HWc + n0 + tx];
        if (mode) {
            float2 sc = *(const float2*)&ss[(bb * Cn + k) * 2];
            v = silu_f(fmaf(v, sc.x, sc.y));
        }
        t[ty + 8 * i][tx] = v;
    }
    __syncthreads();
#pragma unroll
    for (int i = 0; i < 4; i++) {
        int n = n0 + ty + 8 * i;
        float v = t[tx][ty + 8 * i];
        __nv_bfloat16 h = __float2bfloat16(v);
        size_t o = (size_t)bb * CHWc + (size_t)n * Cn + k0 + tx;
        bh[o] = h;
        bl[o] = __float2bfloat16(v - __bfloat162float(h));
    }
}

// ================ k-folded bf16 warp-MMA GEMM ================
// C[b][m][n] = sum_k A[m][k]*Bt[b][n][k]. BM=128, BN=128, BK=32.
// 512 threads = 16 warps (4m x 4n), warp tile 32x32. 8 k-iters; per fragment load,
// 3 products (Ah*Bh, Al*Bh, Ah*Bl) accumulate into one fp32 acc.
#define PITCH 40                 // bf16/row: 80B stride, conflict-free ldmatrix
#define TILE_B (128 * PITCH * 2) // 10240 bytes per (array, stage)
#define OFF_AH 0
#define OFF_AL TILE_B
#define OFF_BH (2*TILE_B)
#define OFF_BL (3*TILE_B)
#define STG (4*TILE_B)           // 40960
#define GSM_TOT (2*STG)          // 81920

__global__ __launch_bounds__(512) void gemm_mma_kernel(
    const __nv_bfloat16* __restrict__ Ah, const __nv_bfloat16* __restrict__ Al,
    const __nv_bfloat16* __restrict__ Bh, const __nv_bfloat16* __restrict__ Bl,
    float* __restrict__ Cd, const float* __restrict__ gbias, int mode)
{
    extern __shared__ __align__(16) char gsm[];
    const uint32_t su = smem_u32(gsm);
    const int tid = threadIdx.x, lane = tid & 31, warp = tid >> 5;
    const int wm = (warp & 3) * 32, wn = (warp >> 2) * 32;
    const int n0 = blockIdx.x * 128, bm = blockIdx.y * 128, bb = blockIdx.z;

    // staging: thread t -> row = t>>2 (0..127), 16B chunk = t&3
    const int s_r = tid >> 2, s_c = (tid & 3);
    const uint32_t s_off = (uint32_t)(s_r * (PITCH * 2) + s_c * 16);
    const size_t a_go = (size_t)(bm + s_r) * 256 + s_c * 8;
    const size_t b_go = ((size_t)bb * HWc + n0 + s_r) * 256 + s_c * 8;

    float acc[2][4][4];
#pragma unroll
    for (int i = 0; i < 2; i++)
#pragma unroll
        for (int j = 0; j < 4; j++)
#pragma unroll
            for (int k = 0; k < 4; k++) acc[i][j][k] = 0.0f;

    // prologue: stages 0 and 1
#pragma unroll
    for (int pre = 0; pre < 2; pre++) {
        const uint32_t sb = su + pre * STG;
        const int k0 = pre * 32;
        cpa16(sb + OFF_AH + s_off, Ah + a_go + k0);
        cpa16(sb + OFF_AL + s_off, Al + a_go + k0);
        cpa16(sb + OFF_BH + s_off, Bh + b_go + k0);
        cpa16(sb + OFF_BL + s_off, Bl + b_go + k0);
        CPA_COMMIT();
    }

    for (int it = 0; it < 8; it++) {
        if (it < 7) CPA_WAIT1(); else CPA_WAIT0();
        __syncthreads();
        const uint32_t sb = su + (it & 1) * STG;
#pragma unroll
        for (int ks = 0; ks < 2; ks++) {
            uint32_t ahf[2][4], alf[2][4], bhf[4][2], blf[4][2];
#pragma unroll
            for (int mt = 0; mt < 2; mt++) {
                uint32_t ao = (uint32_t)(((wm + mt * 16 + (lane & 15)) * PITCH
                                          + ks * 16 + (lane >> 4) * 8) << 1);
                ldsm4(ahf[mt][0], ahf[mt][1], ahf[mt][2], ahf[mt][3], sb + OFF_AH + ao);
                ldsm4(alf[mt][0], alf[mt][1], alf[mt][2], alf[mt][3], sb + OFF_AL + ao);
            }
#pragma unroll
            for (int nt = 0; nt < 4; nt++) {
                uint32_t bo = (uint32_t)(((wn + nt * 8 + (lane & 7)) * PITCH
                                          + ks * 16 + ((lane >> 3) & 1) * 8) << 1);
                ldsm2(bhf[nt][0], bhf[nt][1], sb + OFF_BH + bo);
                ldsm2(blf[nt][0], blf[nt][1], sb + OFF_BL + bo);
            }
#pragma unroll
            for (int mt = 0; mt < 2; mt++)
#pragma unroll
                for (int nt = 0; nt < 4; nt++) {
                    mma16816(acc[mt][nt], ahf[mt], bhf[nt]);
                    mma16816(acc[mt][nt], alf[mt], bhf[nt]);
                    mma16816(acc[mt][nt], ahf[mt], blf[nt]);
                }
        }
        if (it < 6) {
            __syncthreads();
            const int k0 = (it + 2) * 32;
            cpa16(sb + OFF_AH + s_off, Ah + a_go + k0);
            cpa16(sb + OFF_AL + s_off, Al + a_go + k0);
            cpa16(sb + OFF_BH + s_off, Bh + b_go + k0);
            cpa16(sb + OFF_BL + s_off, Bl + b_go + k0);
            CPA_COMMIT();
        }
    }

    // epilogue: fragment rows lane/4 (+8), cols 2*(lane%4)+{0,1}
    const int gr = lane >> 2, gc = (lane & 3) * 2;
#pragma unroll
    for (int mt = 0; mt < 2; mt++) {
        const int row0 = bm + wm + mt * 16 + gr;
        float* p0 = Cd + (size_t)bb * CHWc + (size_t)row0 * HWc + n0 + wn;
        float* p1 = p0 + (size_t)8 * HWc;
        if (mode == 0) {
#pragma unroll
            for (int nt = 0; nt < 4; nt++) {
                *(float2*)(p0 + nt * 8 + gc) = make_float2(acc[mt][nt][0], acc[mt][nt][1]);
                *(float2*)(p1 + nt * 8 + gc) = make_float2(acc[mt][nt][2], acc[mt][nt][3]);
            }
        } else {
            const float gb0 = gbias[row0], gb1 = gbias[row0 + 8];
#pragma unroll
            for (int nt = 0; nt < 4; nt++) {
                *(float2*)(p0 + nt * 8 + gc) =
                    make_float2(sigmoid_f(acc[mt][nt][0] + gb0), sigmoid_f(acc[mt][nt][1] + gb0));
                *(float2*)(p1 + nt * 8 + gc) =
                    make_float2(sigmoid_f(acc[mt][nt][2] + gb1), sigmoid_f(acc[mt][nt][3] + gb1));
            }
        }
    }
}

// ---------------- GroupNorm stats -> per-(b,c) affine ----------------
__global__ __launch_bounds__(1024) void gn_stats_kernel(const float* __restrict__ src,
                                                        const float* __restrict__ gamma,
                                                        const float* __restrict__ beta,
                                                        float* __restrict__ ss)
{
    const int g = blockIdx.x, b = blockIdx.y, tid = threadIdx.x;
    const float4* p = (const float4*)(src + (size_t)b * CHWc + (size_t)g * 16 * HWc);
    float s = 0.0f, s2 = 0.0f;
    const int n4 = 16 * HWc / 4;
    for (int i = tid; i < n4; i += 1024) {
        float4 v = p[i];
        s  += v.x + v.y + v.z + v.w;
        s2 += v.x * v.x + v.y * v.y + v.z * v.z + v.w * v.w;
    }
#pragma unroll
    for (int off = 16; off > 0; off >>= 1) {
        s  += __shfl_xor_sync(0xffffffffu, s, off);
        s2 += __shfl_xor_sync(0xffffffffu, s2, off);
    }
    __shared__ float ws[32], ws2[32];
    __shared__ float mean_s, rstd_s;
    const int wid = tid >> 5, lane = tid & 31;
    if (lane == 0) { ws[wid] = s; ws2[wid] = s2; }
    __syncthreads();
    if (tid < 32) {
        float ts = ws[tid], ts2 = ws2[tid];
#pragma unroll
        for (int off = 16; off > 0; off >>= 1) {
            ts  += __shfl_xor_sync(0xffffffffu, ts, off);
            ts2 += __shfl_xor_sync(0xffffffffu, ts2, off);
        }
        if (tid == 0) {
            const float inv = 1.0f / (16.0f * HWc);
            float mu  = ts * inv;
            float var = ts2 * inv - mu * mu;
            mean_s = mu;
            rstd_s = rsqrtf(var + 1e-5f);
        }
    }
    __syncthreads();
    if (tid < 16) {
        int c = g * 16 + tid;
        float sc = rstd_s * gamma[c];
        ss[(b * Cn + c) * 2 + 0] = sc;
        ss[(b * Cn + c) * 2 + 1] = beta[c] - mean_s * sc;
    }
}

// ---------------- horizontal scans: warp-per-row parallel scan ----------------
__global__ __launch_bounds__(256) void scan_w_kernel(const float* __restrict__ ap,
                                                     const float* __restrict__ bp,
                                                     const float* __restrict__ cp,
                                                     const float* __restrict__ dp)
{
    const int gw = blockIdx.x * 8 + (threadIdx.x >> 5);
    const int lane = threadIdx.x & 31;
    const int bc = gw / Hn;
    const int c  = bc & (Cn - 1);
    const float2 sc = *(const float2*)&g_ss1[bc * 2];
    const float a0 = sigmoid_f(ap[c]),    b0 = bp[c],    c0 = cp[c],    d0 = dp[c];
    const float a1 = sigmoid_f(ap[Cn+c]), b1 = bp[Cn+c], c1 = cp[Cn+c], d1 = dp[Cn+c];
    const float* xr = g_xp + (size_t)gw * Wn;

    float x0 = 0.f, x1 = 0.f, x2 = 0.f, x3 = 0.f;
    if (lane < 24) {
        float4 v = *(const float4*)(xr + lane * 4);
        x0 = silu_f(fmaf(v.x, sc.x, sc.y));
        x1 = silu_f(fmaf(v.y, sc.x, sc.y));
        x2 = silu_f(fmaf(v.z, sc.x, sc.y));
        x3 = silu_f(fmaf(v.w, sc.x, sc.y));
    }
    float a0_4 = (a0 * a0) * (a0 * a0);
    float S = b0 * x0;
    S = fmaf(a0, S, b0 * x1); S = fmaf(a0, S, b0 * x2); S = fmaf(a0, S, b0 * x3);
    float P = a0_4;
#pragma unroll
    for (int off = 1; off < 32; off <<= 1) {
        float Sp = __shfl_up_sync(0xffffffffu, S, off);
        float Pp = __shfl_up_sync(0xffffffffu, P, off);
        if (lane >= off) { S = fmaf(Sp, P, S); P *= Pp; }
    }
    float Hin = __shfl_up_sync(0xffffffffu, S, 1);
    if (lane == 0) Hin = 0.f;
    float hh = Hin;
    hh = fmaf(a0, hh, b0 * x0); float y0 = fmaf(c0, hh, d0 * x0);
    hh = fmaf(a0, hh, b0 * x1); float y1 = fmaf(c0, hh, d0 * x1);
    hh = fmaf(a0, hh, b0 * x2); float y2 = fmaf(c0, hh, d0 * x2);
    hh = fmaf(a0, hh, b0 * x3); float y3 = fmaf(c0, hh, d0 * x3);
    float a1_4 = (a1 * a1) * (a1 * a1);
    float S2 = b1 * x3;
    S2 = fmaf(a1, S2, b1 * x2); S2 = fmaf(a1, S2, b1 * x1); S2 = fmaf(a1, S2, b1 * x0);
    float P2 = a1_4;
    if (lane >= 24) { S2 = 0.f; P2 = 1.f; }
#pragma unroll
    for (int off = 1; off < 32; off <<= 1) {
        float Sp = __shfl_down_sync(0xffffffffu, S2, off);
        float Pp = __shfl_down_sync(0xffffffffu, P2, off);
        if (lane + off < 32) { S2 = fmaf(Sp, P2, S2); P2 *= Pp; }
    }
    float Hin2 = __shfl_down_sync(0xffffffffu, S2, 1);
    if (lane == 31) Hin2 = 0.f;
    hh = Hin2;
    hh = fmaf(a1, hh, b1 * x3); y3 += fmaf(c1, hh, d1 * x3);
    hh = fmaf(a1, hh, b1 * x2); y2 += fmaf(c1, hh, d1 * x2);
    hh = fmaf(a1, hh, b1 * x1); y1 += fmaf(c1, hh, d1 * x1);
    hh = fmaf(a1, hh, b1 * x0); y0 += fmaf(c1, hh, d1 * x0);

    if (lane < 24)
        *(float4*)(g_sw + (size_t)gw * Wn + lane * 4) = make_float4(y0, y1, y2, y3);
}

// ---------------- vertical scans: block per (b,c), thread per column ----------------
// smem holds only the backward partial; x recomputed from L2 on the forward pass.
__global__ __launch_bounds__(96) void scan_h_kernel(const float* __restrict__ ap,
                                                    const float* __restrict__ bp,
                                                    const float* __restrict__ cp,
                                                    const float* __restrict__ dp)
{
    __shared__ float ytmp[HWc];   // 36 KB
    const int bc = blockIdx.x;
    const int c  = bc & (Cn - 1);
    const int tid = threadIdx.x;
    const float2 sc = *(const float2*)&g_ss1[bc * 2];
    const size_t base = (size_t)bc * HWc;

    const float a2 = sigmoid_f(ap[2*Cn+c]), b2 = bp[2*Cn+c], c2 = cp[2*Cn+c], d2 = dp[2*Cn+c];
    const float a3 = sigmoid_f(ap[3*Cn+c]), b3 = bp[3*Cn+c], c3 = cp[3*Cn+c], d3 = dp[3*Cn+c];
    const int w = tid;
    float hs = 0.f;
#pragma unroll 4
    for (int hhi = Hn - 1; hhi >= 0; hhi--) {
        float xv = silu_f(fmaf(g_xp[base + hhi * Wn + w], sc.x, sc.y));
        hs = fmaf(a3, hs, b3 * xv);
        ytmp[hhi * Wn + w] = fmaf(c3, hs, d3 * xv);
    }
    hs = 0.f;
#pragma unroll 4
    for (int hhi = 0; hhi < Hn; hhi++) {
        float xv = silu_f(fmaf(g_xp[base + hhi * Wn + w], sc.x, sc.y));
        hs = fmaf(a2, hs, b2 * xv);
        g_sh[base + hhi * Wn + w] = fmaf(c2, hs, d2 * xv) + ytmp[hhi * Wn + w];
    }
}

// ---------------- fused = 0.25*(sw+sh)*gate, 3x3 depthwise SAME conv ----------------
__global__ __launch_bounds__(256) void fuse_dw_kernel(const float* __restrict__ dww)
{
    __shared__ float ft[34 * 36];
    const int bc = blockIdx.z;
    const int h0 = blockIdx.y * 32, w0 = blockIdx.x * 32;
    const int c = bc & (Cn - 1);
    const size_t base = (size_t)bc * HWc;
    const int tid = threadIdx.x;

    for (int i = tid; i < 34 * 34; i += 256) {
        int r = i / 34, cc = i - r * 34;
        int gh = h0 - 1 + r, gw = w0 - 1 + cc;
        float v = 0.0f;
        if ((unsigned)gh < (unsigned)Hn && (unsigned)gw < (unsigned)Wn) {
            size_t idx = base + gh * Wn + gw;
            v = 0.25f * (g_sw[idx] + g_sh[idx]) * g_gate[idx];
        }
        ft[r * 36 + cc] = v;
    }
    float kw[9];
#pragma unroll
    for (int j = 0; j < 9; j++) kw[j] = dww[c * 9 + j];
    __syncthreads();

    const int tx = tid & 31, ty0 = tid >> 5;
#pragma unroll
    for (int rr = 0; rr < 4; rr++) {
        int r = ty0 + rr * 8;
        float acc = 0.0f;
#pragma unroll
        for (int i = 0; i < 3; i++)
#pragma unroll
            for (int j = 0; j < 3; j++)
                acc = fmaf(ft[(r + i) * 36 + tx + j], kw[i * 3 + j], acc);
        g_fd[base + (size_t)(h0 + r) * Wn + w0 + tx] = acc;
    }
}

// ---------------- final: silu(affine(o1)) -> out ----------------
__global__ __launch_bounds__(256) void finalize_kernel(const float* __restrict__ src,
                                                       const float* __restrict__ ss,
                                                       float* __restrict__ out)
{
    int i4 = blockIdx.x * 256 + threadIdx.x;
    if (i4 >= TOTc / 4) return;
    int bc = i4 / (HWc / 4);
    float2 sc = *(const float2*)&ss[bc * 2];
    float4 v = ((const float4*)src)[i4];
    v.x = silu_f(fmaf(v.x, sc.x, sc.y));
    v.y = silu_f(fmaf(v.y, sc.x, sc.y));
    v.z = silu_f(fmaf(v.z, sc.x, sc.y));
    v.w = silu_f(fmaf(v.w, sc.x, sc.y));
    ((float4*)out)[i4] = v;
}

// ---------------- launch ----------------
extern "C" void kernel_launch(void* const* d_in, const int* in_sizes, int n_in,
                              void* d_out, int out_size)
{
    const float* x      = (const float*)d_in[0];
    const float* in_w   = (const float*)d_in[1];
    const float* gn1_w  = (const float*)d_in[2];
    const float* gn1_b  = (const float*)d_in[3];
    const float* a_p    = (const float*)d_in[4];
    const float* b_p    = (const float*)d_in[5];
    const float* c_p    = (const float*)d_in[6];
    const float* d_p    = (const float*)d_in[7];
    const float* gate_w = (const float*)d_in[8];
    const float* gate_b = (const float*)d_in[9];
    const float* dw_w   = (const float*)d_in[10];
    const float* pw_w   = (const float*)d_in[11];
    const float* gn2_w  = (const float*)d_in[12];
    const float* gn2_b  = (const float*)d_in[13];
    float* out = (float*)d_out;

    float *p_xp, *p_gate, *p_fd, *p_o1, *p_ss1, *p_ss2;
    __nv_bfloat16 *p_bth, *p_btl, *p_ah, *p_al;
    cudaGetSymbolAddress((void**)&p_xp,   g_xp);
    cudaGetSymbolAddress((void**)&p_gate, g_gate);
    cudaGetSymbolAddress((void**)&p_fd,   g_fd);
    cudaGetSymbolAddress((void**)&p_o1,   g_o1);
    cudaGetSymbolAddress((void**)&p_ss1,  g_ss1);
    cudaGetSymbolAddress((void**)&p_ss2,  g_ss2);
    cudaGetSymbolAddress((void**)&p_bth,  g_bth);
    cudaGetSymbolAddress((void**)&p_btl,  g_btl);
    cudaGetSymbolAddress((void**)&p_ah,   g_ahh);
    cudaGetSymbolAddress((void**)&p_al,   g_all);

    cudaFuncSetAttribute(gemm_mma_kernel, cudaFuncAttributeMaxDynamicSharedMemorySize, GSM_TOT);

    dim3 gcv(HWc / 32, Cn / 32, Bn);
    dim3 bcv(32, 8);
    dim3 gmm(HWc / 128, Cn / 128, Bn);

    // convert all three weight matrices up front
    convA3_kernel<<<3 * Cn * Cn / 256, 256>>>(in_w, gate_w, pw_w, p_ah, p_al);

    // GEMM1: xp = in_w @ x
    convT_kernel<<<gcv, bcv>>>(x, p_bth, p_btl, p_ss1, 0);
    gemm_mma_kernel<<<gmm, 512, GSM_TOT>>>(p_ah, p_al, p_bth, p_btl, p_xp, gate_b, 0);
    gn_stats_kernel<<<dim3(16, Bn), 1024>>>(p_xp, gn1_w, gn1_b, p_ss1);

    // gate GEMM: gate = sigmoid(gate_w @ silu(affine(xp)) + b)
    convT_kernel<<<gcv, bcv>>>(p_xp, p_bth, p_btl, p_ss1, 1);
    gemm_mma_kernel<<<gmm, 512, GSM_TOT>>>(p_ah + 65536, p_al + 65536, p_bth, p_btl, p_gate, gate_b, 1);

    // scans + fuse + depthwise
    scan_w_kernel<<<Bn * Cn * Hn / 8, 256>>>(a_p, b_p, c_p, d_p);
    scan_h_kernel<<<Bn * Cn, 96>>>(a_p, b_p, c_p, d_p);
    fuse_dw_kernel<<<dim3(3, 3, Bn * Cn), 256>>>(dw_w);

    // GEMM3: o1 = pw_w @ fd
    convT_kernel<<<gcv, bcv>>>(p_fd, p_bth, p_btl, p_ss1, 0);
    gemm_mma_kernel<<<gmm, 512, GSM_TOT>>>(p_ah + 131072, p_al + 131072, p_bth, p_btl, p_o1, gate_b, 0);

    gn_stats_kernel<<<dim3(16, Bn), 1024>>>(p_o1, gn2_w, gn2_b, p_ss2);
    finalize_kernel<<<(TOTc / 4 + 255) / 256, 256>>>(p_o1, p_ss2, out);
}